// round 7
// baseline (speedup 1.0000x reference)
#include <cuda_runtime.h>
#include <cuda_bf16.h>
#include <math.h>
#include <stdint.h>

// Problem constants
#define BB   2
#define LL   2048
#define DD   1024
#define HH   16
#define HDIM 64

// Scratch (static device memory; allocation-guard safe)
__device__ __align__(256) float g_q[BB * LL * DD];
__device__ __align__(256) float g_k[BB * LL * DD];
__device__ __align__(256) float g_v[BB * LL * DD];
__device__ __align__(256) __nv_bfloat16 g_xhi[BB * LL * DD];
__device__ __align__(256) __nv_bfloat16 g_xlo[BB * LL * DD];
__device__ __align__(256) __nv_bfloat16 g_wthi[3 * DD * DD];
__device__ __align__(256) __nv_bfloat16 g_wtlo[3 * DD * DD];

// ---------------------------------------------------------------------------
// PTX helpers (portable to plain compute_103 target: mma.sync + cp.async)
// ---------------------------------------------------------------------------
__device__ __forceinline__ uint32_t smem_u32(const void* p) {
    uint32_t a;
    asm("{ .reg .u64 t; cvta.to.shared.u64 t, %1; cvt.u32.u64 %0, t; }"
        : "=r"(a) : "l"(p));
    return a;
}

#define CP_ASYNC16(dst, src) \
    asm volatile("cp.async.cg.shared.global [%0], [%1], 16;" \
                 :: "r"(dst), "l"(src) : "memory")
#define CP_COMMIT() asm volatile("cp.async.commit_group;" ::: "memory")
#define CP_WAIT1()  asm volatile("cp.async.wait_group 1;" ::: "memory")

#define LDSM_X4(r0, r1, r2, r3, addr) \
    asm volatile("ldmatrix.sync.aligned.m8n8.x4.shared.b16 {%0,%1,%2,%3}, [%4];" \
                 : "=r"(r0), "=r"(r1), "=r"(r2), "=r"(r3) : "r"(addr))

#define MMA_BF16(d, a, b0, b1) \
    asm volatile("mma.sync.aligned.m16n8k16.row.col.f32.bf16.bf16.f32 " \
                 "{%0,%1,%2,%3}, {%4,%5,%6,%7}, {%8,%9}, {%0,%1,%2,%3};" \
                 : "+f"((d)[0]), "+f"((d)[1]), "+f"((d)[2]), "+f"((d)[3]) \
                 : "r"((a)[0]), "r"((a)[1]), "r"((a)[2]), "r"((a)[3]), \
                   "r"(b0), "r"(b1))

// MUFU-free exp2: magic-constant round + degree-5 poly + exponent splice.
// Valid for x <= ~0 (clamped at -120); rel err ~2.4e-6. ~9 fma/alu ops.
__device__ __forceinline__ float fast_exp2(float x) {
    x = fmaxf(x, -120.0f);
    float t = x + 12582912.0f;              // 2^23 + 2^22: RN to integer
    float f = x - (t - 12582912.0f);        // frac in [-0.5, 0.5]
    float p = 1.0f + f * (0.6931471806f + f * (0.2402265070f +
              f * (0.0555041087f + f * (0.0096181290f + f * 0.0013333558f))));
    return __int_as_float((__float_as_int(t) << 23) + __float_as_int(p));
}

// ---------------------------------------------------------------------------
// Pre-pass 1: split X (fp32) into bf16 hi/lo
// ---------------------------------------------------------------------------
__global__ __launch_bounds__(256) void split_x_kernel(const float* __restrict__ X)
{
    const int total = BB * LL * DD;
    for (int idx = blockIdx.x * blockDim.x * 8 + threadIdx.x; idx < total;
         idx += gridDim.x * blockDim.x * 8) {
#pragma unroll
        for (int s = 0; s < 8; s++) {
            int i = idx + s * 256;
            if (i < total) {
                float x = X[i];
                __nv_bfloat16 hi = __float2bfloat16(x);
                g_xhi[i] = hi;
                g_xlo[i] = __float2bfloat16(x - __bfloat162float(hi));
            }
        }
    }
}

// ---------------------------------------------------------------------------
// Pre-pass 2: transpose W [k][n] -> Wt [n][k], split into bf16 hi/lo
// ---------------------------------------------------------------------------
__global__ __launch_bounds__(256) void wsplit_kernel(
    const float* __restrict__ Wq, const float* __restrict__ Wk,
    const float* __restrict__ Wv)
{
    __shared__ float t[32][33];
    const float* W = (blockIdx.z == 0) ? Wq : (blockIdx.z == 1) ? Wk : Wv;
    const size_t off = (size_t)blockIdx.z * DD * DD;
    int bx = blockIdx.x * 32;   // n tile
    int by = blockIdx.y * 32;   // k tile
#pragma unroll
    for (int j = 0; j < 4; j++)
        t[threadIdx.y + 8 * j][threadIdx.x] =
            W[(size_t)(by + threadIdx.y + 8 * j) * DD + bx + threadIdx.x];
    __syncthreads();
#pragma unroll
    for (int j = 0; j < 4; j++) {
        int n = bx + threadIdx.y + 8 * j;
        int k = by + threadIdx.x;
        float v = t[threadIdx.x][threadIdx.y + 8 * j];
        __nv_bfloat16 hi = __float2bfloat16(v);
        g_wthi[off + (size_t)n * DD + k] = hi;
        g_wtlo[off + (size_t)n * DD + k] = __float2bfloat16(v - __bfloat162float(hi));
    }
}

// ---------------------------------------------------------------------------
// Kernel: QKV GEMM via mma.sync bf16 hi/lo (3 terms). 128x128 tile, BK=32,
// 256 threads = 8 warps as 2(m)x4(n), 64x32 per warp. cp.async 2-stage pipe.
// ---------------------------------------------------------------------------
#define RSTR   80                 // smem row stride, bytes
#define TILE_B (128 * RSTR)
#define STG    (4 * TILE_B)
#define OA_HI  0
#define OA_LO  TILE_B
#define OB_HI  (2 * TILE_B)
#define OB_LO  (3 * TILE_B)
#define GEMM_SMEM (2 * STG)       // 81920 B

__global__ __launch_bounds__(256) void qkv_mma_kernel(
    const float* __restrict__ bq, const float* __restrict__ bk,
    const float* __restrict__ bv)
{
    extern __shared__ char smem[];
    const uint32_t sbase = smem_u32(smem);
    const int tid  = threadIdx.x;
    const int lane = tid & 31;
    const int wid  = tid >> 5;
    const int wm   = wid & 1;
    const int wn   = wid >> 1;

    const int n0  = blockIdx.x * 128;
    const int m0  = blockIdx.y * 128;
    const int mat = blockIdx.z;

    const __nv_bfloat16* Bh = g_wthi + (size_t)mat * DD * DD;
    const __nv_bfloat16* Bl = g_wtlo + (size_t)mat * DD * DD;
    const float* bias = (mat == 0) ? bq : (mat == 1) ? bk : bv;
    float* out = (mat == 0) ? g_q : (mat == 1) ? g_k : g_v;

    const int lr0 = (tid + 0)   >> 2, lc0 = (tid & 3) * 16;
    const int lr1 = (tid + 256) >> 2, lc1 = lc0;

    float acc[4][4][4];
#pragma unroll
    for (int i = 0; i < 4; i++)
#pragma unroll
        for (int j = 0; j < 4; j++)
#pragma unroll
            for (int r = 0; r < 4; r++) acc[i][j][r] = 0.0f;

    auto issue = [&](int c, int s) {
        const uint32_t sb = sbase + s * STG;
        const int k0 = c * 32;
        const int cgk0 = lc0 / 2;
        CP_ASYNC16(sb + OA_HI + lr0 * RSTR + lc0, g_xhi + (size_t)(m0 + lr0) * DD + k0 + cgk0);
        CP_ASYNC16(sb + OA_HI + lr1 * RSTR + lc1, g_xhi + (size_t)(m0 + lr1) * DD + k0 + cgk0);
        CP_ASYNC16(sb + OA_LO + lr0 * RSTR + lc0, g_xlo + (size_t)(m0 + lr0) * DD + k0 + cgk0);
        CP_ASYNC16(sb + OA_LO + lr1 * RSTR + lc1, g_xlo + (size_t)(m0 + lr1) * DD + k0 + cgk0);
        CP_ASYNC16(sb + OB_HI + lr0 * RSTR + lc0, Bh + (size_t)(n0 + lr0) * DD + k0 + cgk0);
        CP_ASYNC16(sb + OB_HI + lr1 * RSTR + lc1, Bh + (size_t)(n0 + lr1) * DD + k0 + cgk0);
        CP_ASYNC16(sb + OB_LO + lr0 * RSTR + lc0, Bl + (size_t)(n0 + lr0) * DD + k0 + cgk0);
        CP_ASYNC16(sb + OB_LO + lr1 * RSTR + lc1, Bl + (size_t)(n0 + lr1) * DD + k0 + cgk0);
    };

    issue(0, 0); CP_COMMIT();
    issue(1, 1); CP_COMMIT();

    const int NCHUNK = DD / 32;   // 32
    for (int c = 0; c < NCHUNK; c++) {
        const int buf = c & 1;
        CP_WAIT1();
        __syncthreads();

        const uint32_t sb = sbase + buf * STG;
        const uint32_t a_row = (wm * 64 + (lane & 15)) * RSTR + (lane >> 4) * 16;
        const uint32_t b_row = (wn * 32 + (lane & 7) + ((lane >> 4) & 1) * 8) * RSTR
                             + ((lane >> 3) & 1) * 16;
#pragma unroll
        for (int ks = 0; ks < 2; ks++) {
            const uint32_t ko = ks * 32;
            uint32_t ahi[4][4], alo[4][4], bhi[8], blo[8];
#pragma unroll
            for (int i = 0; i < 4; i++) {
                LDSM_X4(ahi[i][0], ahi[i][1], ahi[i][2], ahi[i][3],
                        sb + OA_HI + a_row + i * 16 * RSTR + ko);
                LDSM_X4(alo[i][0], alo[i][1], alo[i][2], alo[i][3],
                        sb + OA_LO + a_row + i * 16 * RSTR + ko);
            }
#pragma unroll
            for (int p = 0; p < 2; p++) {
                LDSM_X4(bhi[4 * p], bhi[4 * p + 1], bhi[4 * p + 2], bhi[4 * p + 3],
                        sb + OB_HI + b_row + p * 16 * RSTR + ko);
                LDSM_X4(blo[4 * p], blo[4 * p + 1], blo[4 * p + 2], blo[4 * p + 3],
                        sb + OB_LO + b_row + p * 16 * RSTR + ko);
            }
#pragma unroll
            for (int i = 0; i < 4; i++)
#pragma unroll
                for (int j = 0; j < 4; j++) {
                    const int bb0 = 4 * (j >> 1) + (j & 1) * 2;
                    MMA_BF16(acc[i][j], ahi[i], bhi[bb0], bhi[bb0 + 1]);
                    MMA_BF16(acc[i][j], ahi[i], blo[bb0], blo[bb0 + 1]);
                    MMA_BF16(acc[i][j], alo[i], bhi[bb0], bhi[bb0 + 1]);
                }
        }
        __syncthreads();
        if (c + 2 < NCHUNK) issue(c + 2, buf);
        CP_COMMIT();
    }

    // Epilogue
#pragma unroll
    for (int j = 0; j < 4; j++) {
        const int col = n0 + wn * 32 + j * 8 + (lane & 3) * 2;
        const float b0 = bias[col], b1 = bias[col + 1];
#pragma unroll
        for (int i = 0; i < 4; i++) {
            const int row = m0 + wm * 64 + i * 16 + (lane >> 2);
            *(float2*)(out + (size_t)row * DD + col) =
                make_float2(acc[i][j][0] + b0, acc[i][j][1] + b1);
            *(float2*)(out + (size_t)(row + 8) * DD + col) =
                make_float2(acc[i][j][2] + b0, acc[i][j][3] + b1);
        }
    }
}

// ---------------------------------------------------------------------------
// Kernel: flash attention. BQ=BKV=128, HD=64, 512 threads (16 warps).
// S tile: 8x4 per thread; O tile: 8x2. Softmax uses MUFU-free fast_exp2.
// ---------------------------------------------------------------------------
#define KSTR 66
#define PSTR 132
#define ATTN_SMEM ((3 * 128 * KSTR + 128 * PSTR) * 4)

__global__ __launch_bounds__(512, 1) void attn_kernel(
    const float* __restrict__ mask, float* __restrict__ out)
{
    extern __shared__ float sm[];
    float* Qs = sm;                       // [128][66]
    float* Ks = sm + 128 * KSTR;          // [128][66]
    float* Vs = sm + 2 * 128 * KSTR;      // [128][66]
    float* Ps = sm + 3 * 128 * KSTR;      // [128][132]

    const int b  = blockIdx.z;
    const int h  = blockIdx.y;
    const int qb = blockIdx.x;
    const int tid = threadIdx.x;
    const int ty = tid >> 5;   // warp
    const int tx = tid & 31;   // lane

    const float LOG2E  = 1.4426950408889634f;
    const float QSCALE = 0.125f * LOG2E;
    const float MSCALE = -60.0f * LOG2E;

    const float* qbase = g_q + ((size_t)(b * LL + qb * 128)) * DD + h * HDIM;
    const float* kbase = g_k + ((size_t)b * LL) * DD + h * HDIM;
    const float* vbase = g_v + ((size_t)b * LL) * DD + h * HDIM;
    const float* mbase = mask + (size_t)b * LL * LL + (size_t)(qb * 128) * LL;

    // Load Q tile (128x64), scaled
#pragma unroll
    for (int i = 0; i < 4; i++) {
        int idx = tid + i * 512;
        int r = idx >> 4;
        int c = (idx & 15) * 4;
        float4 v = *(const float4*)(qbase + (size_t)r * DD + c);
        float* dst = &Qs[r * KSTR + c];
        *(float2*)(dst)     = make_float2(v.x * QSCALE, v.y * QSCALE);
        *(float2*)(dst + 2) = make_float2(v.z * QSCALE, v.w * QSCALE);
    }

    float O[8][2];
#pragma unroll
    for (int i = 0; i < 8; i++) { O[i][0] = 0.0f; O[i][1] = 0.0f; }
    float mrow[8], lrow[8];
#pragma unroll
    for (int i = 0; i < 8; i++) { mrow[i] = -INFINITY; lrow[i] = 0.0f; }

    for (int kb = 0; kb < LL / 128; kb++) {
        __syncthreads();
#pragma unroll
        for (int i = 0; i < 4; i++) {
            int idx = tid + i * 512;
            int r = idx >> 4;
            int c = (idx & 15) * 4;
            float4 kv = *(const float4*)(kbase + (size_t)(kb * 128 + r) * DD + c);
            float4 vv = *(const float4*)(vbase + (size_t)(kb * 128 + r) * DD + c);
            float* kd = &Ks[r * KSTR + c];
            float* vd = &Vs[r * KSTR + c];
            *(float2*)(kd)     = make_float2(kv.x, kv.y);
            *(float2*)(kd + 2) = make_float2(kv.z, kv.w);
            *(float2*)(vd)     = make_float2(vv.x, vv.y);
            *(float2*)(vd + 2) = make_float2(vv.z, vv.w);
        }
        __syncthreads();

        // S = Qs @ Ks^T (8x4 per thread)
        float S[8][4];
#pragma unroll
        for (int i = 0; i < 8; i++)
#pragma unroll
            for (int j = 0; j < 4; j++) S[i][j] = 0.0f;

#pragma unroll 8
        for (int d = 0; d < HDIM; d += 2) {
            float2 q[8], k[4];
#pragma unroll
            for (int i = 0; i < 8; i++)
                q[i] = *(const float2*)&Qs[(ty + 16 * i) * KSTR + d];
#pragma unroll
            for (int j = 0; j < 4; j++)
                k[j] = *(const float2*)&Ks[(tx + 32 * j) * KSTR + d];
#pragma unroll
            for (int i = 0; i < 8; i++)
#pragma unroll
                for (int j = 0; j < 4; j++) {
                    S[i][j] = fmaf(q[i].x, k[j].x, S[i][j]);
                    S[i][j] = fmaf(q[i].y, k[j].y, S[i][j]);
                }
        }

        // Add mask * MSCALE (base-2 domain)
#pragma unroll
        for (int i = 0; i < 8; i++) {
            const float* mr_ = mbase + (size_t)(ty + 16 * i) * LL + kb * 128;
#pragma unroll
            for (int j = 0; j < 4; j++)
                S[i][j] = fmaf(mr_[tx + 32 * j], MSCALE, S[i][j]);
        }

        // Online softmax per row (full-warp reductions, MUFU-free exp2)
#pragma unroll
        for (int i = 0; i < 8; i++) {
            float mx = fmaxf(fmaxf(S[i][0], S[i][1]), fmaxf(S[i][2], S[i][3]));
#pragma unroll
            for (int off = 1; off < 32; off <<= 1)
                mx = fmaxf(mx, __shfl_xor_sync(0xffffffffu, mx, off));
            float mnew = fmaxf(mrow[i], mx);
            float corr = fast_exp2(mrow[i] - mnew);
            mrow[i] = mnew;
            float rs = 0.0f;
#pragma unroll
            for (int j = 0; j < 4; j++) {
                S[i][j] = fast_exp2(S[i][j] - mnew);
                rs += S[i][j];
            }
#pragma unroll
            for (int off = 1; off < 32; off <<= 1)
                rs += __shfl_xor_sync(0xffffffffu, rs, off);
            lrow[i] = lrow[i] * corr + rs;
            O[i][0] *= corr;
            O[i][1] *= corr;
            float* pr = &Ps[(ty + 16 * i) * PSTR];
#pragma unroll
            for (int j = 0; j < 4; j++) pr[tx + 32 * j] = S[i][j];
        }
        __syncthreads();

        // O += P @ V
#pragma unroll 2
        for (int j0 = 0; j0 < 128; j0 += 4) {
            float4 p[8];
#pragma unroll
            for (int i = 0; i < 8; i++)
                p[i] = *(const float4*)&Ps[(ty + 16 * i) * PSTR + j0];
#pragma unroll
            for (int jj = 0; jj < 4; jj++) {
                float v0 = Vs[(j0 + jj) * KSTR + tx];
                float v1 = Vs[(j0 + jj) * KSTR + tx + 32];
#pragma unroll
                for (int i = 0; i < 8; i++) {
                    float pi = (jj == 0) ? p[i].x : (jj == 1) ? p[i].y
                             : (jj == 2) ? p[i].z : p[i].w;
                    O[i][0] = fmaf(pi, v0, O[i][0]);
                    O[i][1] = fmaf(pi, v1, O[i][1]);
                }
            }
        }
    }

    // Epilogue
    float* obase = out + ((size_t)(b * LL + qb * 128)) * DD + h * HDIM;
#pragma unroll
    for (int i = 0; i < 8; i++) {
        float inv = __frcp_rn(lrow[i]);
        obase[(size_t)(ty + 16 * i) * DD + tx]      = O[i][0] * inv;
        obase[(size_t)(ty + 16 * i) * DD + tx + 32] = O[i][1] * inv;
    }
}

// ---------------------------------------------------------------------------
// Launcher
// ---------------------------------------------------------------------------
extern "C" void kernel_launch(void* const* d_in, const int* in_sizes, int n_in,
                              void* d_out, int out_size)
{
    const float* x    = (const float*)d_in[0];
    const float* mask = (const float*)d_in[1];
    const float* Wq   = (const float*)d_in[2];
    const float* bq   = (const float*)d_in[3];
    const float* Wk   = (const float*)d_in[4];
    const float* bk   = (const float*)d_in[5];
    const float* Wv   = (const float*)d_in[6];
    const float* bv   = (const float*)d_in[7];
    float* out = (float*)d_out;

    split_x_kernel<<<2048, 256>>>(x);
    wsplit_kernel<<<dim3(32, 32, 3), dim3(32, 8)>>>(Wq, Wk, Wv);

    cudaFuncSetAttribute(qkv_mma_kernel,
                         cudaFuncAttributeMaxDynamicSharedMemorySize, GEMM_SMEM);
    qkv_mma_kernel<<<dim3(8, 32, 3), 256, GEMM_SMEM>>>(bq, bk, bv);

    cudaFuncSetAttribute(attn_kernel,
                         cudaFuncAttributeMaxDynamicSharedMemorySize, ATTN_SMEM);
    attn_kernel<<<dim3(16, 16, 2), 512, ATTN_SMEM>>>(mask, out);
}

// round 9
// speedup vs baseline: 1.1589x; 1.1589x over previous
#include <cuda_runtime.h>
#include <cuda_bf16.h>
#include <math.h>
#include <stdint.h>

// Problem constants
#define BB   2
#define LL   2048
#define DD   1024
#define HH   16
#define HDIM 64

// Scratch (static device memory; allocation-guard safe)
__device__ __align__(256) float g_q[BB * LL * DD];
__device__ __align__(256) float g_k[BB * LL * DD];
__device__ __align__(256) float g_v[BB * LL * DD];
__device__ __align__(256) __nv_bfloat16 g_xhi[BB * LL * DD];
__device__ __align__(256) __nv_bfloat16 g_xlo[BB * LL * DD];
__device__ __align__(256) __nv_bfloat16 g_wthi[3 * DD * DD];
__device__ __align__(256) __nv_bfloat16 g_wtlo[3 * DD * DD];

// ---------------------------------------------------------------------------
// PTX helpers
// ---------------------------------------------------------------------------
__device__ __forceinline__ uint32_t smem_u32(const void* p) {
    uint32_t a;
    asm("{ .reg .u64 t; cvta.to.shared.u64 t, %1; cvt.u32.u64 %0, t; }"
        : "=r"(a) : "l"(p));
    return a;
}

#define CP_ASYNC16(dst, src) \
    asm volatile("cp.async.cg.shared.global [%0], [%1], 16;" \
                 :: "r"(dst), "l"(src) : "memory")
#define CP_COMMIT() asm volatile("cp.async.commit_group;" ::: "memory")
#define CP_WAIT1()  asm volatile("cp.async.wait_group 1;" ::: "memory")

#define LDSM_X4(r0, r1, r2, r3, addr) \
    asm volatile("ldmatrix.sync.aligned.m8n8.x4.shared.b16 {%0,%1,%2,%3}, [%4];" \
                 : "=r"(r0), "=r"(r1), "=r"(r2), "=r"(r3) : "r"(addr))

#define MMA_BF16(d, a, b0, b1) \
    asm volatile("mma.sync.aligned.m16n8k16.row.col.f32.bf16.bf16.f32 " \
                 "{%0,%1,%2,%3}, {%4,%5,%6,%7}, {%8,%9}, {%0,%1,%2,%3};" \
                 : "+f"((d)[0]), "+f"((d)[1]), "+f"((d)[2]), "+f"((d)[3]) \
                 : "r"((a)[0]), "r"((a)[1]), "r"((a)[2]), "r"((a)[3]), \
                   "r"(b0), "r"(b1))

// Packed f32x2 (Blackwell, base sm_100+ PTX; ptxas never auto-fuses these)
#define FFMA2(d, a, b) \
    asm("fma.rn.f32x2 %0, %1, %2, %0;" : "+l"(d) : "l"(a), "l"(b))
#define FMUL2(d, a) \
    asm("mul.rn.f32x2 %0, %0, %1;" : "+l"(d) : "l"(a))

__device__ __forceinline__ uint64_t pack2(float lo, float hi) {
    uint64_t d;
    asm("mov.b64 %0, {%1, %2};" : "=l"(d) : "f"(lo), "f"(hi));
    return d;
}
__device__ __forceinline__ void unpack2(uint64_t v, float& lo, float& hi) {
    asm("mov.b64 {%0, %1}, %2;" : "=f"(lo), "=f"(hi) : "l"(v));
}

// ---------------------------------------------------------------------------
// Pre-pass 1: split X (fp32) into bf16 hi/lo
// ---------------------------------------------------------------------------
__global__ __launch_bounds__(256) void split_x_kernel(const float* __restrict__ X)
{
    const int total = BB * LL * DD;
    for (int idx = blockIdx.x * blockDim.x * 8 + threadIdx.x; idx < total;
         idx += gridDim.x * blockDim.x * 8) {
#pragma unroll
        for (int s = 0; s < 8; s++) {
            int i = idx + s * 256;
            if (i < total) {
                float x = X[i];
                __nv_bfloat16 hi = __float2bfloat16(x);
                g_xhi[i] = hi;
                g_xlo[i] = __float2bfloat16(x - __bfloat162float(hi));
            }
        }
    }
}

// ---------------------------------------------------------------------------
// Pre-pass 2: transpose W [k][n] -> Wt [n][k], split into bf16 hi/lo
// ---------------------------------------------------------------------------
__global__ __launch_bounds__(256) void wsplit_kernel(
    const float* __restrict__ Wq, const float* __restrict__ Wk,
    const float* __restrict__ Wv)
{
    __shared__ float t[32][33];
    const float* W = (blockIdx.z == 0) ? Wq : (blockIdx.z == 1) ? Wk : Wv;
    const size_t off = (size_t)blockIdx.z * DD * DD;
    int bx = blockIdx.x * 32;   // n tile
    int by = blockIdx.y * 32;   // k tile
#pragma unroll
    for (int j = 0; j < 4; j++)
        t[threadIdx.y + 8 * j][threadIdx.x] =
            W[(size_t)(by + threadIdx.y + 8 * j) * DD + bx + threadIdx.x];
    __syncthreads();
#pragma unroll
    for (int j = 0; j < 4; j++) {
        int n = bx + threadIdx.y + 8 * j;
        int k = by + threadIdx.x;
        float v = t[threadIdx.x][threadIdx.y + 8 * j];
        __nv_bfloat16 hi = __float2bfloat16(v);
        g_wthi[off + (size_t)n * DD + k] = hi;
        g_wtlo[off + (size_t)n * DD + k] = __float2bfloat16(v - __bfloat162float(hi));
    }
}

// ---------------------------------------------------------------------------
// Kernel: QKV GEMM via mma.sync bf16 hi/lo (3 terms). 128x128 tile, BK=32,
// 256 threads = 8 warps as 2(m)x4(n), 64x32 per warp. cp.async 2-stage pipe.
// ---------------------------------------------------------------------------
#define RSTR   80                 // smem row stride, bytes
#define TILE_B (128 * RSTR)
#define STG    (4 * TILE_B)
#define OA_HI  0
#define OA_LO  TILE_B
#define OB_HI  (2 * TILE_B)
#define OB_LO  (3 * TILE_B)
#define GEMM_SMEM (2 * STG)       // 81920 B

__global__ __launch_bounds__(256) void qkv_mma_kernel(
    const float* __restrict__ bq, const float* __restrict__ bk,
    const float* __restrict__ bv)
{
    extern __shared__ char smem[];
    const uint32_t sbase = smem_u32(smem);
    const int tid  = threadIdx.x;
    const int lane = tid & 31;
    const int wid  = tid >> 5;
    const int wm   = wid & 1;
    const int wn   = wid >> 1;

    const int n0  = blockIdx.x * 128;
    const int m0  = blockIdx.y * 128;
    const int mat = blockIdx.z;

    const __nv_bfloat16* Bh = g_wthi + (size_t)mat * DD * DD;
    const __nv_bfloat16* Bl = g_wtlo + (size_t)mat * DD * DD;
    const float* bias = (mat == 0) ? bq : (mat == 1) ? bk : bv;
    float* out = (mat == 0) ? g_q : (mat == 1) ? g_k : g_v;

    const int lr0 = (tid + 0)   >> 2, lc0 = (tid & 3) * 16;
    const int lr1 = (tid + 256) >> 2, lc1 = lc0;

    float acc[4][4][4];
#pragma unroll
    for (int i = 0; i < 4; i++)
#pragma unroll
        for (int j = 0; j < 4; j++)
#pragma unroll
            for (int r = 0; r < 4; r++) acc[i][j][r] = 0.0f;

    auto issue = [&](int c, int s) {
        const uint32_t sb = sbase + s * STG;
        const int k0 = c * 32;
        const int cgk0 = lc0 / 2;
        CP_ASYNC16(sb + OA_HI + lr0 * RSTR + lc0, g_xhi + (size_t)(m0 + lr0) * DD + k0 + cgk0);
        CP_ASYNC16(sb + OA_HI + lr1 * RSTR + lc1, g_xhi + (size_t)(m0 + lr1) * DD + k0 + cgk0);
        CP_ASYNC16(sb + OA_LO + lr0 * RSTR + lc0, g_xlo + (size_t)(m0 + lr0) * DD + k0 + cgk0);
        CP_ASYNC16(sb + OA_LO + lr1 * RSTR + lc1, g_xlo + (size_t)(m0 + lr1) * DD + k0 + cgk0);
        CP_ASYNC16(sb + OB_HI + lr0 * RSTR + lc0, Bh + (size_t)(n0 + lr0) * DD + k0 + cgk0);
        CP_ASYNC16(sb + OB_HI + lr1 * RSTR + lc1, Bh + (size_t)(n0 + lr1) * DD + k0 + cgk0);
        CP_ASYNC16(sb + OB_LO + lr0 * RSTR + lc0, Bl + (size_t)(n0 + lr0) * DD + k0 + cgk0);
        CP_ASYNC16(sb + OB_LO + lr1 * RSTR + lc1, Bl + (size_t)(n0 + lr1) * DD + k0 + cgk0);
    };

    issue(0, 0); CP_COMMIT();
    issue(1, 1); CP_COMMIT();

    const int NCHUNK = DD / 32;   // 32
    for (int c = 0; c < NCHUNK; c++) {
        const int buf = c & 1;
        CP_WAIT1();
        __syncthreads();

        const uint32_t sb = sbase + buf * STG;
        const uint32_t a_row = (wm * 64 + (lane & 15)) * RSTR + (lane >> 4) * 16;
        const uint32_t b_row = (wn * 32 + (lane & 7) + ((lane >> 4) & 1) * 8) * RSTR
                             + ((lane >> 3) & 1) * 16;
#pragma unroll
        for (int ks = 0; ks < 2; ks++) {
            const uint32_t ko = ks * 32;
            uint32_t ahi[4][4], alo[4][4], bhi[8], blo[8];
#pragma unroll
            for (int i = 0; i < 4; i++) {
                LDSM_X4(ahi[i][0], ahi[i][1], ahi[i][2], ahi[i][3],
                        sb + OA_HI + a_row + i * 16 * RSTR + ko);
                LDSM_X4(alo[i][0], alo[i][1], alo[i][2], alo[i][3],
                        sb + OA_LO + a_row + i * 16 * RSTR + ko);
            }
#pragma unroll
            for (int p = 0; p < 2; p++) {
                LDSM_X4(bhi[4 * p], bhi[4 * p + 1], bhi[4 * p + 2], bhi[4 * p + 3],
                        sb + OB_HI + b_row + p * 16 * RSTR + ko);
                LDSM_X4(blo[4 * p], blo[4 * p + 1], blo[4 * p + 2], blo[4 * p + 3],
                        sb + OB_LO + b_row + p * 16 * RSTR + ko);
            }
#pragma unroll
            for (int i = 0; i < 4; i++)
#pragma unroll
                for (int j = 0; j < 4; j++) {
                    const int bb0 = 4 * (j >> 1) + (j & 1) * 2;
                    MMA_BF16(acc[i][j], ahi[i], bhi[bb0], bhi[bb0 + 1]);
                    MMA_BF16(acc[i][j], ahi[i], blo[bb0], blo[bb0 + 1]);
                    MMA_BF16(acc[i][j], alo[i], bhi[bb0], bhi[bb0 + 1]);
                }
        }
        __syncthreads();
        if (c + 2 < NCHUNK) issue(c + 2, buf);
        CP_COMMIT();
    }

    // Epilogue
#pragma unroll
    for (int j = 0; j < 4; j++) {
        const int col = n0 + wn * 32 + j * 8 + (lane & 3) * 2;
        const float b0 = bias[col], b1 = bias[col + 1];
#pragma unroll
        for (int i = 0; i < 4; i++) {
            const int row = m0 + wm * 64 + i * 16 + (lane >> 2);
            *(float2*)(out + (size_t)row * DD + col) =
                make_float2(acc[i][j][0] + b0, acc[i][j][1] + b1);
            *(float2*)(out + (size_t)(row + 8) * DD + col) =
                make_float2(acc[i][j][2] + b0, acc[i][j][3] + b1);
        }
    }
}

// ---------------------------------------------------------------------------
// Kernel: flash attention. BQ=BKV=128, HD=64, 512 threads (16 warps).
// S tile: 8x4 per thread (rows ty+16i, cols tx+32j) via packed FFMA2 over d.
// O tile: 8 rows x 2 adjacent cols {2tx, 2tx+1}, one packed f32x2 per row.
// ---------------------------------------------------------------------------
#define KSTR 66
#define PSTR 132
#define ATTN_SMEM ((3 * 128 * KSTR + 128 * PSTR) * 4)

__global__ __launch_bounds__(512, 1) void attn_kernel(
    const float* __restrict__ mask, float* __restrict__ out)
{
    extern __shared__ float sm[];
    float* Qs = sm;                       // [128][66]
    float* Ks = sm + 128 * KSTR;          // [128][66]
    float* Vs = sm + 2 * 128 * KSTR;      // [128][66]
    float* Ps = sm + 3 * 128 * KSTR;      // [128][132]

    const int b  = blockIdx.z;
    const int h  = blockIdx.y;
    const int qb = blockIdx.x;
    const int tid = threadIdx.x;
    const int ty = tid >> 5;   // warp
    const int tx = tid & 31;   // lane

    const float LOG2E  = 1.4426950408889634f;
    const float QSCALE = 0.125f * LOG2E;
    const float MSCALE = -60.0f * LOG2E;

    const float* qbase = g_q + ((size_t)(b * LL + qb * 128)) * DD + h * HDIM;
    const float* kbase = g_k + ((size_t)b * LL) * DD + h * HDIM;
    const float* vbase = g_v + ((size_t)b * LL) * DD + h * HDIM;
    const float* mbase = mask + (size_t)b * LL * LL + (size_t)(qb * 128) * LL;

    // Load Q tile (128x64), scaled
#pragma unroll
    for (int i = 0; i < 4; i++) {
        int idx = tid + i * 512;
        int r = idx >> 4;
        int c = (idx & 15) * 4;
        float4 v = *(const float4*)(qbase + (size_t)r * DD + c);
        float* dst = &Qs[r * KSTR + c];
        *(float2*)(dst)     = make_float2(v.x * QSCALE, v.y * QSCALE);
        *(float2*)(dst + 2) = make_float2(v.z * QSCALE, v.w * QSCALE);
    }

    uint64_t O2[8];
#pragma unroll
    for (int i = 0; i < 8; i++) O2[i] = 0ull;
    float mrow[8], lrow[8];
#pragma unroll
    for (int i = 0; i < 8; i++) { mrow[i] = -INFINITY; lrow[i] = 0.0f; }

    for (int kb = 0; kb < LL / 128; kb++) {
        __syncthreads();
#pragma unroll
        for (int i = 0; i < 4; i++) {
            int idx = tid + i * 512;
            int r = idx >> 4;
            int c = (idx & 15) * 4;
            float4 kv = *(const float4*)(kbase + (size_t)(kb * 128 + r) * DD + c);
            float4 vv = *(const float4*)(vbase + (size_t)(kb * 128 + r) * DD + c);
            float* kd = &Ks[r * KSTR + c];
            float* vd = &Vs[r * KSTR + c];
            *(float2*)(kd)     = make_float2(kv.x, kv.y);
            *(float2*)(kd + 2) = make_float2(kv.z, kv.w);
            *(float2*)(vd)     = make_float2(vv.x, vv.y);
            *(float2*)(vd + 2) = make_float2(vv.z, vv.w);
        }
        __syncthreads();

        // S = Qs @ Ks^T, packed over even/odd d (FFMA2): 1024 instr vs 2048
        uint64_t S2[8][4];
#pragma unroll
        for (int i = 0; i < 8; i++)
#pragma unroll
            for (int j = 0; j < 4; j++) S2[i][j] = 0ull;

#pragma unroll 4
        for (int d = 0; d < HDIM; d += 2) {
            uint64_t q2[8], k2[4];
#pragma unroll
            for (int i = 0; i < 8; i++)
                q2[i] = *(const uint64_t*)&Qs[(ty + 16 * i) * KSTR + d];
#pragma unroll
            for (int j = 0; j < 4; j++)
                k2[j] = *(const uint64_t*)&Ks[(tx + 32 * j) * KSTR + d];
#pragma unroll
            for (int i = 0; i < 8; i++)
#pragma unroll
                for (int j = 0; j < 4; j++)
                    FFMA2(S2[i][j], q2[i], k2[j]);
        }

        // Unpack (S = lo+hi) and add mask * MSCALE
        float S[8][4];
#pragma unroll
        for (int i = 0; i < 8; i++) {
            const float* mr_ = mbase + (size_t)(ty + 16 * i) * LL + kb * 128;
#pragma unroll
            for (int j = 0; j < 4; j++) {
                float lo, hi;
                unpack2(S2[i][j], lo, hi);
                S[i][j] = fmaf(mr_[tx + 32 * j], MSCALE, lo + hi);
            }
        }

        // Online softmax per row (full-warp reductions; exp2f on MUFU)
#pragma unroll
        for (int i = 0; i < 8; i++) {
            float mx = fmaxf(fmaxf(S[i][0], S[i][1]), fmaxf(S[i][2], S[i][3]));
#pragma unroll
            for (int off = 1; off < 32; off <<= 1)
                mx = fmaxf(mx, __shfl_xor_sync(0xffffffffu, mx, off));
            float mnew = fmaxf(mrow[i], mx);
            float corr = exp2f(mrow[i] - mnew);
            mrow[i] = mnew;
            float rs = 0.0f;
#pragma unroll
            for (int j = 0; j < 4; j++) {
                S[i][j] = exp2f(S[i][j] - mnew);
                rs += S[i][j];
            }
#pragma unroll
            for (int off = 1; off < 32; off <<= 1)
                rs += __shfl_xor_sync(0xffffffffu, rs, off);
            lrow[i] = lrow[i] * corr + rs;
            FMUL2(O2[i], pack2(corr, corr));
            float* pr = &Ps[(ty + 16 * i) * PSTR];
#pragma unroll
            for (int j = 0; j < 4; j++) pr[tx + 32 * j] = S[i][j];
        }
        __syncthreads();

        // O += P @ V  (cols 2tx, 2tx+1 packed; FFMA2 halves PV FFMA count)
#pragma unroll 2
        for (int j0 = 0; j0 < 128; j0 += 4) {
            float4 p[8];
#pragma unroll
            for (int i = 0; i < 8; i++)
                p[i] = *(const float4*)&Ps[(ty + 16 * i) * PSTR + j0];
#pragma unroll
            for (int jj = 0; jj < 4; jj++) {
                uint64_t v2 = *(const uint64_t*)&Vs[(j0 + jj) * KSTR + 2 * tx];
#pragma unroll
                for (int i = 0; i < 8; i++) {
                    float pi = (jj == 0) ? p[i].x : (jj == 1) ? p[i].y
                             : (jj == 2) ? p[i].z : p[i].w;
                    FFMA2(O2[i], pack2(pi, pi), v2);
                }
            }
        }
    }

    // Epilogue: cols 2tx, 2tx+1 (contiguous float2 per thread)
    float* obase = out + ((size_t)(b * LL + qb * 128)) * DD + h * HDIM;
#pragma unroll
    for (int i = 0; i < 8; i++) {
        float inv = __frcp_rn(lrow[i]);
        float o0, o1;
        unpack2(O2[i], o0, o1);
        *(float2*)(obase + (size_t)(ty + 16 * i) * DD + 2 * tx) =
            make_float2(o0 * inv, o1 * inv);
    }
}

// ---------------------------------------------------------------------------
// Launcher
// ---------------------------------------------------------------------------
extern "C" void kernel_launch(void* const* d_in, const int* in_sizes, int n_in,
                              void* d_out, int out_size)
{
    const float* x    = (const float*)d_in[0];
    const float* mask = (const float*)d_in[1];
    const float* Wq   = (const float*)d_in[2];
    const float* bq   = (const float*)d_in[3];
    const float* Wk   = (const float*)d_in[4];
    const float* bk   = (const float*)d_in[5];
    const float* Wv   = (const float*)d_in[6];
    const float* bv   = (const float*)d_in[7];
    float* out = (float*)d_out;

    split_x_kernel<<<2048, 256>>>(x);
    wsplit_kernel<<<dim3(32, 32, 3), dim3(32, 8)>>>(Wq, Wk, Wv);

    cudaFuncSetAttribute(qkv_mma_kernel,
                         cudaFuncAttributeMaxDynamicSharedMemorySize, GEMM_SMEM);
    qkv_mma_kernel<<<dim3(8, 32, 3), 256, GEMM_SMEM>>>(bq, bk, bv);

    cudaFuncSetAttribute(attn_kernel,
                         cudaFuncAttributeMaxDynamicSharedMemorySize, ATTN_SMEM);
    attn_kernel<<<dim3(16, 16, 2), 512, ATTN_SMEM>>>(mask, out);
}